// round 7
// baseline (speedup 1.0000x reference)
#include <cuda_runtime.h>

// Problem constants
#define Bb 2
#define Hh 16
#define Tt 2048
#define Kk 64
#define Vv 64
#define Cc 64                 // chunk length
#define NCk (Tt/Cc)           // 32 chunks
#define BH (Bb*Hh)            // 32
#define OUT_T_SIZE (BH*Tt*Vv) // floats of 'out' before state_f

// ---------------- scratch (static __device__, no allocation) ----------------
__device__ float g_aC[BH*NCk*Kk];                   // chunk total decay     256KB
__device__ float g_dS[(size_t)BH*NCk*Kk*Vv];        // chunk state delta     16MB
__device__ float g_Sc[(size_t)BH*NCk*Kk*Vv];        // state at chunk start  16MB

// ---------------- helpers ----------------
__device__ __forceinline__ void cp_async16(void* smem_dst, const void* gmem_src) {
    unsigned sa = (unsigned)__cvta_generic_to_shared(smem_dst);
    asm volatile("cp.async.cg.shared.global [%0], [%1], 16;" :: "r"(sa), "l"(gmem_src));
}
__device__ __forceinline__ void cp_async_wait_all() {
    asm volatile("cp.async.commit_group;");
    asm volatile("cp.async.wait_group 0;");
}

// 4 independent warp-inclusive product scans (componentwise over lanes)
__device__ __forceinline__ float4 warp_prod_scan4(float4 a) {
    const int lane = threadIdx.x & 31;
    #pragma unroll
    for (int off = 1; off < 32; off <<= 1) {
        float x0 = __shfl_up_sync(0xffffffffu, a.x, off);
        float x1 = __shfl_up_sync(0xffffffffu, a.y, off);
        float x2 = __shfl_up_sync(0xffffffffu, a.z, off);
        float x3 = __shfl_up_sync(0xffffffffu, a.w, off);
        if (lane >= off) { a.x *= x0; a.y *= x1; a.z *= x2; a.w *= x3; }
    }
    return a;
}
__device__ __forceinline__ float4 shfl_up1_or_one4(float4 a) {
    const int lane = threadIdx.x & 31;
    float4 r;
    r.x = __shfl_up_sync(0xffffffffu, a.x, 1);
    r.y = __shfl_up_sync(0xffffffffu, a.y, 1);
    r.z = __shfl_up_sync(0xffffffffu, a.z, 1);
    r.w = __shfl_up_sync(0xffffffffu, a.w, 1);
    if (lane == 0) r = make_float4(1.f, 1.f, 1.f, 1.f);
    return r;
}
__device__ __forceinline__ float4 shfl31_4(float4 a) {
    float4 r;
    r.x = __shfl_sync(0xffffffffu, a.x, 31);
    r.y = __shfl_sync(0xffffffffu, a.y, 31);
    r.z = __shfl_sync(0xffffffffu, a.z, 31);
    r.w = __shfl_sync(0xffffffffu, a.w, 31);
    return r;
}
__device__ __forceinline__ float4 fmax4(float4 a, float e) {
    return make_float4(fmaxf(a.x, e), fmaxf(a.y, e), fmaxf(a.z, e), fmaxf(a.w, e));
}

// ================= kernel 1: suffix decays + delta-state GEMM =================
// dS[k][v] = sum_i sfx_i[k] * k_i[k] * v_i[v],  sfx_i = prod_{j=i+1..63} w_j (<=1, safe)
struct K1Smem {
    float w[Cc][68];
    float k[Cc][68];   // raw k -> sfx*k in place
    float v[Cc][Vv];
};

__global__ __launch_bounds__(256, 4) void k1_chunk(
    const float* __restrict__ k, const float* __restrict__ v,
    const float* __restrict__ w)
{
    extern __shared__ char smem_raw[];
    K1Smem& sm = *reinterpret_cast<K1Smem*>(smem_raw);

    const int bh = blockIdx.y;
    const int h  = bh & (Hh - 1);
    const int tid  = threadIdx.x;
    const int lane = tid & 31;
    const int wi   = tid >> 5;

    #pragma unroll 1
    for (int half = 0; half < 2; half++) {
        const int c  = blockIdx.x + half * (NCk / 2);
        const int t0 = c * Cc;

        // ---- stage w, k, v via cp.async (coalesced float4) ----
        {
            const float4* wp = (const float4*)(w + ((size_t)h  * Tt + t0) * Kk);
            const float4* kp = (const float4*)(k + ((size_t)bh * Tt + t0) * Kk);
            const float4* vp = (const float4*)(v + ((size_t)bh * Tt + t0) * Vv);
            #pragma unroll
            for (int i = tid; i < Cc * Kk / 4; i += 256) {
                int t = i >> 4, k0 = (i & 15) * 4;
                cp_async16(&sm.w[t][k0], &wp[i]);
                cp_async16(&sm.k[t][k0], &kp[i]);
                cp_async16(&((float4*)sm.v)[i], &vp[i]);
            }
            cp_async_wait_all();
        }
        __syncthreads();

        // ---- vec4 suffix scan: each warp owns 8 k-columns (2 groups of 4) ----
        #pragma unroll
        for (int g = 0; g < 2; g++) {
            const int kk4 = wi * 8 + g * 4;
            // half A: rows 63..32 (reversed)
            float4 wA = fmax4(*(const float4*)&sm.w[63 - lane][kk4], 1e-6f);
            float4 sA   = warp_prod_scan4(wA);          // prod rows [63-lane..63]
            float4 sfxA = shfl_up1_or_one4(sA);
            float4 T0   = shfl31_4(sA);                 // prod rows [32..63]
            float4 kA = *(const float4*)&sm.k[63 - lane][kk4];
            kA.x *= sfxA.x; kA.y *= sfxA.y; kA.z *= sfxA.z; kA.w *= sfxA.w;
            *(float4*)&sm.k[63 - lane][kk4] = kA;
            // half B: rows 31..0 (reversed)
            float4 wB = fmax4(*(const float4*)&sm.w[31 - lane][kk4], 1e-6f);
            float4 sB   = warp_prod_scan4(wB);          // prod rows [31-lane..31]
            float4 sfxB = shfl_up1_or_one4(sB);
            float4 kB = *(const float4*)&sm.k[31 - lane][kk4];
            kB.x *= sfxB.x * T0.x; kB.y *= sfxB.y * T0.y;
            kB.z *= sfxB.z * T0.z; kB.w *= sfxB.w * T0.w;
            *(float4*)&sm.k[31 - lane][kk4] = kB;
            if (lane == 31) {
                float4 aC;
                aC.x = sB.x * T0.x; aC.y = sB.y * T0.y;
                aC.z = sB.z * T0.z; aC.w = sB.w * T0.w;
                *(float4*)&g_aC[(bh * NCk + c) * Kk + kk4] = aC;
            }
        }
        __syncthreads();

        // ---- delta-state GEMM (64k x 64v over 64t), 4x4 tile per thread ----
        const int tk = (tid >> 4) * 4;
        const int tv = (tid & 15) * 4;
        float acc[4][4];
        #pragma unroll
        for (int a = 0; a < 4; a++)
            #pragma unroll
            for (int b = 0; b < 4; b++) acc[a][b] = 0.0f;

        #pragma unroll 8
        for (int t = 0; t < Cc; t++) {
            float4 ka = *(const float4*)&sm.k[t][tk];
            float4 va = *(const float4*)&sm.v[t][tv];
            float kr[4] = {ka.x, ka.y, ka.z, ka.w};
            float vr[4] = {va.x, va.y, va.z, va.w};
            #pragma unroll
            for (int a = 0; a < 4; a++)
                #pragma unroll
                for (int b = 0; b < 4; b++)
                    acc[a][b] = fmaf(kr[a], vr[b], acc[a][b]);
        }

        float* dsp = g_dS + (size_t)(bh * NCk + c) * Kk * Vv;
        #pragma unroll
        for (int a = 0; a < 4; a++)
            *(float4*)&dsp[(size_t)(tk + a) * Vv + tv] =
                make_float4(acc[a][0], acc[a][1], acc[a][2], acc[a][3]);
        __syncthreads();   // before restaging next chunk
    }
}

// ================= kernel 2: sequential chunk-level state scan =================
__global__ __launch_bounds__(256) void k2_scan(
    const float* __restrict__ state_in, float* __restrict__ out)
{
    const int bh  = blockIdx.y;
    const int tid = threadIdx.x;
    const int fi  = blockIdx.x * 256 + tid;    // float4 index in [0,1024)
    const int krow = fi >> 4;

    float4 S = ((const float4*)(state_in + (size_t)bh * Kk * Vv))[fi];

    const float*  aCb = g_aC + bh * NCk * Kk;
    const float4* dSb = (const float4*)(g_dS + (size_t)bh * NCk * Kk * Vv);
    float4*       Scb = (float4*)(g_Sc + (size_t)bh * NCk * Kk * Vv);

    float4 db[2][4];
    float  ab[2][4];

    #pragma unroll
    for (int j = 0; j < 4; j++) {
        db[0][j] = dSb[(size_t)j * 1024 + fi];
        ab[0][j] = aCb[j * Kk + krow];
    }

    #pragma unroll 1
    for (int g = 0; g < NCk / 4; g++) {
        const int cur = g & 1;
        if (g + 1 < NCk / 4) {
            #pragma unroll
            for (int j = 0; j < 4; j++) {
                int c = (g + 1) * 4 + j;
                db[cur ^ 1][j] = dSb[(size_t)c * 1024 + fi];
                ab[cur ^ 1][j] = aCb[c * Kk + krow];
            }
        }
        #pragma unroll
        for (int j = 0; j < 4; j++) {
            int c = g * 4 + j;
            Scb[(size_t)c * 1024 + fi] = S;
            float a = ab[cur][j]; float4 d = db[cur][j];
            S.x = fmaf(a, S.x, d.x); S.y = fmaf(a, S.y, d.y);
            S.z = fmaf(a, S.z, d.z); S.w = fmaf(a, S.w, d.w);
        }
    }

    ((float4*)(out + (size_t)OUT_T_SIZE + (size_t)bh * Kk * Vv))[fi] = S;
}

// ================= kernel 3: outputs =================
// Stage row-major (conflict-free); scan reads rows into regs, then writes
// TRANSPOSED (lane-consecutive => conflict-free) into buffers aliasing the
// dead inputs. Mid-chunk normalization m = prod(rows 0..31) per k-column:
//   r~_i = r_i*prefix_i (<=1);  r^ = r~ * inv_m (on the fly in GEMM1)
//   k^_j = k_j*m/incl_j;  P[i][j] = r^.k^ (j<i), diag (j==i), 0;  O = r~.S + P.v
struct K3Smem {
    float S[Kk][Vv];                                          // 16384
    union { float w_rm[Cc][68]; float rtT[Kk][68]; } A;       // 17408
    union { float r_rm[Cc][68]; float khT[Kk][68];
            float PT[Cc][68]; } B;                            // 17408
    union { float k_rm[Cc][68]; float v[Cc][Vv]; } C;         // 17408
    float dp[8][66];                                          // 2112
    float diag[Cc];                                           // 256
    float inv_m[Kk];                                          // 256
};

__global__ __launch_bounds__(256, 3) void k3_out(
    const float* __restrict__ r, const float* __restrict__ k,
    const float* __restrict__ v, const float* __restrict__ w,
    const float* __restrict__ u, float* __restrict__ out)
{
    extern __shared__ char smem_raw[];
    K3Smem& sm = *reinterpret_cast<K3Smem*>(smem_raw);

    const int bh = blockIdx.y;
    const int h  = bh & (Hh - 1);
    const int tid  = threadIdx.x;
    const int lane = tid & 31;
    const int wi   = tid >> 5;

    #pragma unroll 1
    for (int half = 0; half < 2; half++) {
        const int c  = blockIdx.x + half * (NCk / 2);
        const int t0 = c * Cc;

        // ---- stage S + r,k,w row-major via cp.async ----
        {
            const float4* Sp = (const float4*)(g_Sc + (size_t)(bh * NCk + c) * Kk * Vv);
            #pragma unroll
            for (int p = 0; p < 4; p++)
                cp_async16(&((float4*)sm.S)[p * 256 + tid], &Sp[p * 256 + tid]);
            const float4* rp = (const float4*)(r + ((size_t)bh * Tt + t0) * Kk);
            const float4* kp = (const float4*)(k + ((size_t)bh * Tt + t0) * Kk);
            const float4* wp = (const float4*)(w + ((size_t)h  * Tt + t0) * Kk);
            #pragma unroll
            for (int i = tid; i < Cc * Kk / 4; i += 256) {
                int t = i >> 4, k0 = (i & 15) * 4;
                cp_async16(&sm.A.w_rm[t][k0], &wp[i]);
                cp_async16(&sm.B.r_rm[t][k0], &rp[i]);
                cp_async16(&sm.C.k_rm[t][k0], &kp[i]);
            }
            cp_async_wait_all();
        }
        __syncthreads();

        // ---- scan phase: read rows into regs, compute, hold results ----
        float4 rt0[2], rt1[2], kh0[2], kh1[2], mg[2];
        {
            float dA = 0.0f, dB = 0.0f;
            #pragma unroll
            for (int g = 0; g < 2; g++) {
                const int kk4 = wi * 8 + g * 4;
                float4 w0 = fmax4(*(const float4*)&sm.A.w_rm[lane][kk4],      1e-6f);
                float4 w1 = fmax4(*(const float4*)&sm.A.w_rm[32 + lane][kk4], 1e-6f);
                float4 r0 = *(const float4*)&sm.B.r_rm[lane][kk4];
                float4 r1 = *(const float4*)&sm.B.r_rm[32 + lane][kk4];
                float4 c0 = *(const float4*)&sm.C.k_rm[lane][kk4];
                float4 c1 = *(const float4*)&sm.C.k_rm[32 + lane][kk4];

                float4 p = warp_prod_scan4(w0);     // incl prefix rows 0..lane
                float4 q = warp_prod_scan4(w1);     // incl prefix rows 32..32+lane
                float4 m    = shfl31_4(p);          // prod rows 0..31
                float4 pre  = shfl_up1_or_one4(p);
                float4 pre2 = shfl_up1_or_one4(q);
                float4 u4 = *(const float4*)&u[h * Kk + kk4];

                dA = fmaf(r0.x * c0.x, u4.x, dA); dA = fmaf(r0.y * c0.y, u4.y, dA);
                dA = fmaf(r0.z * c0.z, u4.z, dA); dA = fmaf(r0.w * c0.w, u4.w, dA);
                dB = fmaf(r1.x * c1.x, u4.x, dB); dB = fmaf(r1.y * c1.y, u4.y, dB);
                dB = fmaf(r1.z * c1.z, u4.z, dB); dB = fmaf(r1.w * c1.w, u4.w, dB);

                rt0[g] = make_float4(r0.x * pre.x, r0.y * pre.y, r0.z * pre.z, r0.w * pre.w);
                rt1[g] = make_float4(r1.x * (m.x * pre2.x), r1.y * (m.y * pre2.y),
                                     r1.z * (m.z * pre2.z), r1.w * (m.w * pre2.w));
                kh0[g] = make_float4(c0.x * m.x / p.x, c0.y * m.y / p.y,
                                     c0.z * m.z / p.z, c0.w * m.w / p.w);
                kh1[g] = make_float4(c1.x / q.x, c1.y / q.y, c1.z / q.z, c1.w / q.w);
                mg[g]  = m;
            }
            sm.dp[wi][lane]      = dA;
            sm.dp[wi][32 + lane] = dB;
        }
        __syncthreads();   // ALL row-major reads complete before transposed writes

        // ---- transposed conflict-free writes (lane-consecutive) ----
        #pragma unroll
        for (int g = 0; g < 2; g++) {
            const int kk4 = wi * 8 + g * 4;
            sm.A.rtT[kk4 + 0][lane] = rt0[g].x; sm.A.rtT[kk4 + 1][lane] = rt0[g].y;
            sm.A.rtT[kk4 + 2][lane] = rt0[g].z; sm.A.rtT[kk4 + 3][lane] = rt0[g].w;
            sm.A.rtT[kk4 + 0][32 + lane] = rt1[g].x; sm.A.rtT[kk4 + 1][32 + lane] = rt1[g].y;
            sm.A.rtT[kk4 + 2][32 + lane] = rt1[g].z; sm.A.rtT[kk4 + 3][32 + lane] = rt1[g].w;
            sm.B.khT[kk4 + 0][lane] = kh0[g].x; sm.B.khT[kk4 + 1][lane] = kh0[g].y;
            sm.B.khT[kk4 + 2][lane] = kh0[g].z; sm.B.khT[kk4 + 3][lane] = kh0[g].w;
            sm.B.khT[kk4 + 0][32 + lane] = kh1[g].x; sm.B.khT[kk4 + 1][32 + lane] = kh1[g].y;
            sm.B.khT[kk4 + 2][32 + lane] = kh1[g].z; sm.B.khT[kk4 + 3][32 + lane] = kh1[g].w;
            if (lane == 0) {
                sm.inv_m[kk4 + 0] = 1.0f / mg[g].x; sm.inv_m[kk4 + 1] = 1.0f / mg[g].y;
                sm.inv_m[kk4 + 2] = 1.0f / mg[g].z; sm.inv_m[kk4 + 3] = 1.0f / mg[g].w;
            }
        }
        __syncthreads();
        if (tid < Cc) {
            float d = 0.0f;
            #pragma unroll
            for (int j = 0; j < 8; j++) d += sm.dp[j][tid];
            sm.diag[tid] = d;
        }
        __syncthreads();

        // ---- GEMM1: P[i][j] = (r~_i * inv_m) . k^_j  (4x4 tile) ----
        const int i4 = (tid >> 4) * 4;      // t rows
        const int j4 = (tid & 15) * 4;      // tau cols
        float acc[4][4];
        #pragma unroll
        for (int a = 0; a < 4; a++)
            #pragma unroll
            for (int b = 0; b < 4; b++) acc[a][b] = 0.0f;

        #pragma unroll 8
        for (int kk = 0; kk < Kk; kk++) {
            float im = sm.inv_m[kk];
            float4 ra = *(const float4*)&sm.A.rtT[kk][i4];
            float4 kb = *(const float4*)&sm.B.khT[kk][j4];
            float rr[4] = {ra.x * im, ra.y * im, ra.z * im, ra.w * im};
            float kc[4] = {kb.x, kb.y, kb.z, kb.w};
            #pragma unroll
            for (int a = 0; a < 4; a++)
                #pragma unroll
                for (int b = 0; b < 4; b++)
                    acc[a][b] = fmaf(rr[a], kc[b], acc[a][b]);
        }
        // preload v into registers while other warps finish GEMM1
        float4 vreg[4];
        {
            const float4* vp = (const float4*)(v + ((size_t)bh * Tt + t0) * Vv);
            #pragma unroll
            for (int p = 0; p < 4; p++) vreg[p] = vp[p * 256 + tid];
        }
        float dg[4];
        #pragma unroll
        for (int a = 0; a < 4; a++) dg[a] = sm.diag[i4 + a];

        __syncthreads();   // all reads of rtT(scaled)/khT complete

        // write masked P^T (into B union) and v (into C union)
        #pragma unroll
        for (int b = 0; b < 4; b++) {
            int j = j4 + b;
            float vals[4];
            #pragma unroll
            for (int a = 0; a < 4; a++) {
                int i = i4 + a;
                vals[a] = (j < i) ? acc[a][b] : ((j == i) ? dg[a] : 0.0f);
            }
            *(float4*)&sm.B.PT[j][i4] = make_float4(vals[0], vals[1], vals[2], vals[3]);
        }
        #pragma unroll
        for (int p = 0; p < 4; p++) ((float4*)sm.C.v)[p * 256 + tid] = vreg[p];
        __syncthreads();

        // ---- GEMM2: O[t][v] = r~ . S + P . v  (4x4 tile, all-vector loads) ----
        const int t4 = i4;
        const int v4 = j4;
        #pragma unroll
        for (int a = 0; a < 4; a++)
            #pragma unroll
            for (int b = 0; b < 4; b++) acc[a][b] = 0.0f;

        #pragma unroll 8
        for (int kk = 0; kk < Kk; kk++) {
            float4 ra = *(const float4*)&sm.A.rtT[kk][t4];
            float4 sv = *(const float4*)&sm.S[kk][v4];
            float rr[4] = {ra.x, ra.y, ra.z, ra.w};
            float ss[4] = {sv.x, sv.y, sv.z, sv.w};
            #pragma unroll
            for (int a = 0; a < 4; a++)
                #pragma unroll
                for (int b = 0; b < 4; b++)
                    acc[a][b] = fmaf(rr[a], ss[b], acc[a][b]);
        }
        #pragma unroll 8
        for (int j = 0; j < Cc; j++) {
            float4 pa = *(const float4*)&sm.B.PT[j][t4];
            float4 vv = *(const float4*)&sm.C.v[j][v4];
            float pp[4] = {pa.x, pa.y, pa.z, pa.w};
            float vr[4] = {vv.x, vv.y, vv.z, vv.w};
            #pragma unroll
            for (int a = 0; a < 4; a++)
                #pragma unroll
                for (int b = 0; b < 4; b++)
                    acc[a][b] = fmaf(pp[a], vr[b], acc[a][b]);
        }

        float* op = out + ((size_t)bh * Tt + t0) * Vv;
        #pragma unroll
        for (int a = 0; a < 4; a++)
            *(float4*)&op[(size_t)(t4 + a) * Vv + v4] =
                make_float4(acc[a][0], acc[a][1], acc[a][2], acc[a][3]);
        __syncthreads();   // before restaging next chunk
    }
}

// ---------------- launch ----------------
extern "C" void kernel_launch(void* const* d_in, const int* in_sizes, int n_in,
                              void* d_out, int out_size)
{
    const float* r  = (const float*)d_in[0];
    const float* k  = (const float*)d_in[1];
    const float* v  = (const float*)d_in[2];
    const float* w  = (const float*)d_in[3];
    const float* u  = (const float*)d_in[4];
    const float* st = (const float*)d_in[5];
    float* out = (float*)d_out;

    static bool configured = false;
    if (!configured) {
        cudaFuncSetAttribute(k1_chunk, cudaFuncAttributeMaxDynamicSharedMemorySize,
                             (int)sizeof(K1Smem));
        cudaFuncSetAttribute(k3_out, cudaFuncAttributeMaxDynamicSharedMemorySize,
                             (int)sizeof(K3Smem));
        configured = true;
    }

    k1_chunk<<<dim3(NCk / 2, BH), 256, sizeof(K1Smem)>>>(k, v, w);
    k2_scan<<<dim3(4, BH), 256>>>(st, out);
    k3_out<<<dim3(NCk / 2, BH), 256, sizeof(K3Smem)>>>(r, k, v, w, u, out);
}

// round 9
// speedup vs baseline: 1.3016x; 1.3016x over previous
#include <cuda_runtime.h>

// Problem constants
#define Bb 2
#define Hh 16
#define Tt 2048
#define Kk 64
#define Vv 64
#define Cc 64                 // chunk length
#define NCk (Tt/Cc)           // 32 chunks
#define BH (Bb*Hh)            // 32
#define OUT_T_SIZE (BH*Tt*Vv) // floats of 'out' before state_f

// ---------------- scratch (static __device__, no allocation) ----------------
__device__ float g_aC[BH*NCk*Kk];                   // chunk total decay
__device__ float g_dS[(size_t)BH*NCk*Kk*Vv];        // chunk state delta
__device__ float g_Sc[(size_t)BH*NCk*Kk*Vv];        // state at chunk start

// ---------------- helpers ----------------
__device__ __forceinline__ void cp_async16(void* smem_dst, const void* gmem_src) {
    unsigned sa = (unsigned)__cvta_generic_to_shared(smem_dst);
    asm volatile("cp.async.cg.shared.global [%0], [%1], 16;" :: "r"(sa), "l"(gmem_src));
}
__device__ __forceinline__ void cp_async_wait_all() {
    asm volatile("cp.async.commit_group;");
    asm volatile("cp.async.wait_group 0;");
}

__device__ __forceinline__ unsigned tf32_of(float x) {
    unsigned u;
    asm("cvt.rna.tf32.f32 %0, %1;" : "=r"(u) : "f"(x));
    return u;
}

// D(16x8) += A(16x8,row) * B(8x8,col) ; tf32 inputs, fp32 accumulate
__device__ __forceinline__ void mma16n8k8(float* d,
    unsigned a0, unsigned a1, unsigned a2, unsigned a3,
    unsigned b0, unsigned b1)
{
    asm volatile(
        "mma.sync.aligned.m16n8k8.row.col.f32.tf32.tf32.f32 "
        "{%0,%1,%2,%3}, {%4,%5,%6,%7}, {%8,%9}, {%0,%1,%2,%3};"
        : "+f"(d[0]), "+f"(d[1]), "+f"(d[2]), "+f"(d[3])
        : "r"(a0), "r"(a1), "r"(a2), "r"(a3), "r"(b0), "r"(b1));
}

// 4 independent warp-inclusive product scans (componentwise over lanes)
__device__ __forceinline__ float4 warp_prod_scan4(float4 a) {
    const int lane = threadIdx.x & 31;
    #pragma unroll
    for (int off = 1; off < 32; off <<= 1) {
        float x0 = __shfl_up_sync(0xffffffffu, a.x, off);
        float x1 = __shfl_up_sync(0xffffffffu, a.y, off);
        float x2 = __shfl_up_sync(0xffffffffu, a.z, off);
        float x3 = __shfl_up_sync(0xffffffffu, a.w, off);
        if (lane >= off) { a.x *= x0; a.y *= x1; a.z *= x2; a.w *= x3; }
    }
    return a;
}
__device__ __forceinline__ float4 shfl_up1_or_one4(float4 a) {
    const int lane = threadIdx.x & 31;
    float4 r;
    r.x = __shfl_up_sync(0xffffffffu, a.x, 1);
    r.y = __shfl_up_sync(0xffffffffu, a.y, 1);
    r.z = __shfl_up_sync(0xffffffffu, a.z, 1);
    r.w = __shfl_up_sync(0xffffffffu, a.w, 1);
    if (lane == 0) r = make_float4(1.f, 1.f, 1.f, 1.f);
    return r;
}
__device__ __forceinline__ float4 shfl31_4(float4 a) {
    float4 r;
    r.x = __shfl_sync(0xffffffffu, a.x, 31);
    r.y = __shfl_sync(0xffffffffu, a.y, 31);
    r.z = __shfl_sync(0xffffffffu, a.z, 31);
    r.w = __shfl_sync(0xffffffffu, a.w, 31);
    return r;
}
__device__ __forceinline__ float4 fmax4(float4 a, float e) {
    return make_float4(fmaxf(a.x, e), fmaxf(a.y, e), fmaxf(a.z, e), fmaxf(a.w, e));
}

// ================= kernel 1: suffix decays + delta-state MMA =================
// dS[k][v] = sum_t sfx_t[k]*k_t[k] * v_t[v],  sfx_t = prod_{j>t} w_j (<=1, safe)
struct K1Smem {
    float w[Cc][68];
    float k[Cc][68];   // raw k -> sfx*k in place
    float v[Cc][68];   // padded to 68 for conflict-free fragment loads
};

__global__ __launch_bounds__(256, 4) void k1_chunk(
    const float* __restrict__ k, const float* __restrict__ v,
    const float* __restrict__ w)
{
    extern __shared__ char smem_raw[];
    K1Smem& sm = *reinterpret_cast<K1Smem*>(smem_raw);

    const int bh = blockIdx.y;
    const int h  = bh & (Hh - 1);
    const int tid  = threadIdx.x;
    const int lane = tid & 31;
    const int wi   = tid >> 5;
    const int g  = lane >> 2;      // mma groupID
    const int tg = lane & 3;       // mma thread-in-group
    const int mw = (wi & 3) * 16;  // warp output row base (k dim)
    const int nw = (wi >> 2) * 32; // warp output col base (v dim)

    #pragma unroll 1
    for (int half = 0; half < 2; half++) {
        const int c  = blockIdx.x + half * (NCk / 2);
        const int t0 = c * Cc;

        // ---- stage w, k, v via cp.async ----
        {
            const float4* wp = (const float4*)(w + ((size_t)h  * Tt + t0) * Kk);
            const float4* kp = (const float4*)(k + ((size_t)bh * Tt + t0) * Kk);
            const float4* vp = (const float4*)(v + ((size_t)bh * Tt + t0) * Vv);
            #pragma unroll
            for (int i = tid; i < Cc * Kk / 4; i += 256) {
                int t = i >> 4, k0 = (i & 15) * 4;
                cp_async16(&sm.w[t][k0], &wp[i]);
                cp_async16(&sm.k[t][k0], &kp[i]);
                cp_async16(&sm.v[t][k0], &vp[i]);
            }
            cp_async_wait_all();
        }
        __syncthreads();

        // ---- vec4 suffix scan: each warp owns 8 k-columns ----
        #pragma unroll
        for (int gg = 0; gg < 2; gg++) {
            const int kk4 = wi * 8 + gg * 4;
            float4 wA = fmax4(*(const float4*)&sm.w[63 - lane][kk4], 1e-6f);
            float4 sA   = warp_prod_scan4(wA);
            float4 sfxA = shfl_up1_or_one4(sA);
            float4 T0   = shfl31_4(sA);                 // prod rows [32..63]
            float4 kA = *(const float4*)&sm.k[63 - lane][kk4];
            kA.x *= sfxA.x; kA.y *= sfxA.y; kA.z *= sfxA.z; kA.w *= sfxA.w;
            *(float4*)&sm.k[63 - lane][kk4] = kA;
            float4 wB = fmax4(*(const float4*)&sm.w[31 - lane][kk4], 1e-6f);
            float4 sB   = warp_prod_scan4(wB);
            float4 sfxB = shfl_up1_or_one4(sB);
            float4 kB = *(const float4*)&sm.k[31 - lane][kk4];
            kB.x *= sfxB.x * T0.x; kB.y *= sfxB.y * T0.y;
            kB.z *= sfxB.z * T0.z; kB.w *= sfxB.w * T0.w;
            *(float4*)&sm.k[31 - lane][kk4] = kB;
            if (lane == 31) {
                float4 aC;
                aC.x = sB.x * T0.x; aC.y = sB.y * T0.y;
                aC.z = sB.z * T0.z; aC.w = sB.w * T0.w;
                *(float4*)&g_aC[(bh * NCk + c) * Kk + kk4] = aC;
            }
        }
        __syncthreads();

        // ---- dS MMA: out[k][v], reduction over t. A[m=k][kd=t]=sm.k[t][k]
        float acc[4][4];
        #pragma unroll
        for (int nt = 0; nt < 4; nt++)
            #pragma unroll
            for (int q = 0; q < 4; q++) acc[nt][q] = 0.0f;

        #pragma unroll
        for (int ks = 0; ks < 8; ks++) {
            const int t0r = ks * 8 + tg;
            const int t1r = t0r + 4;
            unsigned a0 = tf32_of(sm.k[t0r][mw + g]);
            unsigned a1 = tf32_of(sm.k[t0r][mw + g + 8]);
            unsigned a2 = tf32_of(sm.k[t1r][mw + g]);
            unsigned a3 = tf32_of(sm.k[t1r][mw + g + 8]);
            #pragma unroll
            for (int nt = 0; nt < 4; nt++) {
                unsigned b0 = tf32_of(sm.v[t0r][nw + nt * 8 + g]);
                unsigned b1 = tf32_of(sm.v[t1r][nw + nt * 8 + g]);
                mma16n8k8(acc[nt], a0, a1, a2, a3, b0, b1);
            }
        }

        float* dsp = g_dS + (size_t)(bh * NCk + c) * Kk * Vv;
        #pragma unroll
        for (int nt = 0; nt < 4; nt++) {
            int col = nw + nt * 8 + 2 * tg;
            *(float2*)&dsp[(size_t)(mw + g)     * Vv + col] = make_float2(acc[nt][0], acc[nt][1]);
            *(float2*)&dsp[(size_t)(mw + g + 8) * Vv + col] = make_float2(acc[nt][2], acc[nt][3]);
        }
        __syncthreads();
    }
}

// ================= kernel 2: sequential chunk-level state scan =================
__global__ __launch_bounds__(256) void k2_scan(
    const float* __restrict__ state_in, float* __restrict__ out)
{
    const int bh  = blockIdx.y;
    const int tid = threadIdx.x;
    const int fi  = blockIdx.x * 256 + tid;
    const int krow = fi >> 4;

    float4 S = ((const float4*)(state_in + (size_t)bh * Kk * Vv))[fi];

    const float*  aCb = g_aC + bh * NCk * Kk;
    const float4* dSb = (const float4*)(g_dS + (size_t)bh * NCk * Kk * Vv);
    float4*       Scb = (float4*)(g_Sc + (size_t)bh * NCk * Kk * Vv);

    float4 db[2][4];
    float  ab[2][4];

    #pragma unroll
    for (int j = 0; j < 4; j++) {
        db[0][j] = dSb[(size_t)j * 1024 + fi];
        ab[0][j] = aCb[j * Kk + krow];
    }

    #pragma unroll 1
    for (int gq = 0; gq < NCk / 4; gq++) {
        const int cur = gq & 1;
        if (gq + 1 < NCk / 4) {
            #pragma unroll
            for (int j = 0; j < 4; j++) {
                int c = (gq + 1) * 4 + j;
                db[cur ^ 1][j] = dSb[(size_t)c * 1024 + fi];
                ab[cur ^ 1][j] = aCb[c * Kk + krow];
            }
        }
        #pragma unroll
        for (int j = 0; j < 4; j++) {
            int c = gq * 4 + j;
            Scb[(size_t)c * 1024 + fi] = S;
            float a = ab[cur][j]; float4 d = db[cur][j];
            S.x = fmaf(a, S.x, d.x); S.y = fmaf(a, S.y, d.y);
            S.z = fmaf(a, S.z, d.z); S.w = fmaf(a, S.w, d.w);
        }
    }

    ((float4*)(out + (size_t)OUT_T_SIZE + (size_t)bh * Kk * Vv))[fi] = S;
}

// ================= kernel 3: outputs (tf32 MMA) =================
struct K3Smem {
    float S[Kk][68];                                          // padded
    union { float w_rm[Cc][68]; float rtT[Kk][68]; } A;
    union { float r_rm[Cc][68]; float khT[Kk][68];
            float PT[Cc][68]; } B;
    union { float k_rm[Cc][68]; float v[Cc][68]; } C;
    float dp[8][66];
    float diag[Cc];
    float inv_m[Kk];
};

__global__ __launch_bounds__(256, 3) void k3_out(
    const float* __restrict__ r, const float* __restrict__ k,
    const float* __restrict__ v, const float* __restrict__ w,
    const float* __restrict__ u, float* __restrict__ out)
{
    extern __shared__ char smem_raw[];
    K3Smem& sm = *reinterpret_cast<K3Smem*>(smem_raw);

    const int bh = blockIdx.y;
    const int h  = bh & (Hh - 1);
    const int tid  = threadIdx.x;
    const int lane = tid & 31;
    const int wi   = tid >> 5;
    const int g  = lane >> 2;
    const int tg = lane & 3;
    const int mw = (wi & 3) * 16;
    const int nw = (wi >> 2) * 32;

    #pragma unroll 1
    for (int half = 0; half < 2; half++) {
        const int c  = blockIdx.x + half * (NCk / 2);
        const int t0 = c * Cc;

        // ---- stage S + r,k,w row-major via cp.async ----
        {
            const float4* Sp = (const float4*)(g_Sc + (size_t)(bh * NCk + c) * Kk * Vv);
            #pragma unroll
            for (int p = 0; p < 4; p++) {
                int f = p * 256 + tid;
                int kr = f >> 4, v0 = (f & 15) * 4;
                cp_async16(&sm.S[kr][v0], &Sp[f]);
            }
            const float4* rp = (const float4*)(r + ((size_t)bh * Tt + t0) * Kk);
            const float4* kp = (const float4*)(k + ((size_t)bh * Tt + t0) * Kk);
            const float4* wp = (const float4*)(w + ((size_t)h  * Tt + t0) * Kk);
            #pragma unroll
            for (int i = tid; i < Cc * Kk / 4; i += 256) {
                int t = i >> 4, k0 = (i & 15) * 4;
                cp_async16(&sm.A.w_rm[t][k0], &wp[i]);
                cp_async16(&sm.B.r_rm[t][k0], &rp[i]);
                cp_async16(&sm.C.k_rm[t][k0], &kp[i]);
            }
            cp_async_wait_all();
        }
        __syncthreads();

        // ---- scan phase (rows -> regs) ----
        float4 rt0[2], rt1[2], kh0[2], kh1[2], mg[2];
        {
            float dA = 0.0f, dB = 0.0f;
            #pragma unroll
            for (int gg = 0; gg < 2; gg++) {
                const int kk4 = wi * 8 + gg * 4;
                float4 w0 = fmax4(*(const float4*)&sm.A.w_rm[lane][kk4],      1e-6f);
                float4 w1 = fmax4(*(const float4*)&sm.A.w_rm[32 + lane][kk4], 1e-6f);
                float4 r0 = *(const float4*)&sm.B.r_rm[lane][kk4];
                float4 r1 = *(const float4*)&sm.B.r_rm[32 + lane][kk4];
                float4 c0 = *(const float4*)&sm.C.k_rm[lane][kk4];
                float4 c1 = *(const float4*)&sm.C.k_rm[32 + lane][kk4];

                float4 p = warp_prod_scan4(w0);
                float4 q = warp_prod_scan4(w1);
                float4 m    = shfl31_4(p);
                float4 pre  = shfl_up1_or_one4(p);
                float4 pre2 = shfl_up1_or_one4(q);
                float4 u4 = *(const float4*)&u[h * Kk + kk4];

                dA = fmaf(r0.x * c0.x, u4.x, dA); dA = fmaf(r0.y * c0.y, u4.y, dA);
                dA = fmaf(r0.z * c0.z, u4.z, dA); dA = fmaf(r0.w * c0.w, u4.w, dA);
                dB = fmaf(r1.x * c1.x, u4.x, dB); dB = fmaf(r1.y * c1.y, u4.y, dB);
                dB = fmaf(r1.z * c1.z, u4.z, dB); dB = fmaf(r1.w * c1.w, u4.w, dB);

                rt0[gg] = make_float4(r0.x * pre.x, r0.y * pre.y, r0.z * pre.z, r0.w * pre.w);
                rt1[gg] = make_float4(r1.x * (m.x * pre2.x), r1.y * (m.y * pre2.y),
                                      r1.z * (m.z * pre2.z), r1.w * (m.w * pre2.w));
                kh0[gg] = make_float4(c0.x * m.x / p.x, c0.y * m.y / p.y,
                                      c0.z * m.z / p.z, c0.w * m.w / p.w);
                kh1[gg] = make_float4(c1.x / q.x, c1.y / q.y, c1.z / q.z, c1.w / q.w);
                mg[gg]  = m;
            }
            sm.dp[wi][lane]      = dA;
            sm.dp[wi][32 + lane] = dB;
        }
        __syncthreads();   // row-major reads complete before transposed writes

        // ---- transposed conflict-free writes ----
        #pragma unroll
        for (int gg = 0; gg < 2; gg++) {
            const int kk4 = wi * 8 + gg * 4;
            sm.A.rtT[kk4 + 0][lane] = rt0[gg].x; sm.A.rtT[kk4 + 1][lane] = rt0[gg].y;
            sm.A.rtT[kk4 + 2][lane] = rt0[gg].z; sm.A.rtT[kk4 + 3][lane] = rt0[gg].w;
            sm.A.rtT[kk4 + 0][32 + lane] = rt1[gg].x; sm.A.rtT[kk4 + 1][32 + lane] = rt1[gg].y;
            sm.A.rtT[kk4 + 2][32 + lane] = rt1[gg].z; sm.A.rtT[kk4 + 3][32 + lane] = rt1[gg].w;
            sm.B.khT[kk4 + 0][lane] = kh0[gg].x; sm.B.khT[kk4 + 1][lane] = kh0[gg].y;
            sm.B.khT[kk4 + 2][lane] = kh0[gg].z; sm.B.khT[kk4 + 3][lane] = kh0[gg].w;
            sm.B.khT[kk4 + 0][32 + lane] = kh1[gg].x; sm.B.khT[kk4 + 1][32 + lane] = kh1[gg].y;
            sm.B.khT[kk4 + 2][32 + lane] = kh1[gg].z; sm.B.khT[kk4 + 3][32 + lane] = kh1[gg].w;
            if (lane == 0) {
                sm.inv_m[kk4 + 0] = 1.0f / mg[gg].x; sm.inv_m[kk4 + 1] = 1.0f / mg[gg].y;
                sm.inv_m[kk4 + 2] = 1.0f / mg[gg].z; sm.inv_m[kk4 + 3] = 1.0f / mg[gg].w;
            }
        }
        __syncthreads();
        if (tid < Cc) {
            float d = 0.0f;
            #pragma unroll
            for (int j = 0; j < 8; j++) d += sm.dp[j][tid];
            sm.diag[tid] = d;
        }
        __syncthreads();

        // ---- GEMM1 (MMA): P[i][j] = sum_k (rtT[k][i]*inv_m[k]) * khT[k][j] ----
        float acc[4][4];
        #pragma unroll
        for (int nt = 0; nt < 4; nt++)
            #pragma unroll
            for (int q = 0; q < 4; q++) acc[nt][q] = 0.0f;

        #pragma unroll
        for (int ks = 0; ks < 8; ks++) {
            const int k0 = ks * 8 + tg;
            const int k1r = k0 + 4;
            float im0 = sm.inv_m[k0], im1 = sm.inv_m[k1r];
            unsigned a0 = tf32_of(sm.A.rtT[k0][mw + g]      * im0);
            unsigned a1 = tf32_of(sm.A.rtT[k0][mw + g + 8]  * im0);
            unsigned a2 = tf32_of(sm.A.rtT[k1r][mw + g]     * im1);
            unsigned a3 = tf32_of(sm.A.rtT[k1r][mw + g + 8] * im1);
            #pragma unroll
            for (int nt = 0; nt < 4; nt++) {
                unsigned b0 = tf32_of(sm.B.khT[k0][nw + nt * 8 + g]);
                unsigned b1 = tf32_of(sm.B.khT[k1r][nw + nt * 8 + g]);
                mma16n8k8(acc[nt], a0, a1, a2, a3, b0, b1);
            }
        }

        // preload v while other warps finish GEMM1; read diag
        float4 vreg[4];
        {
            const float4* vp = (const float4*)(v + ((size_t)bh * Tt + t0) * Vv);
            #pragma unroll
            for (int p = 0; p < 4; p++) vreg[p] = vp[p * 256 + tid];
        }
        float dg0 = sm.diag[mw + g];
        float dg1 = sm.diag[mw + g + 8];

        __syncthreads();   // all reads of rtT/khT complete

        // ---- mask + store P^T (aliases khT) and v (aliases k_rm) ----
        #pragma unroll
        for (int nt = 0; nt < 4; nt++) {
            int jb = nw + nt * 8 + 2 * tg;
            int i0 = mw + g, i1 = mw + g + 8;
            float p00 = (jb     < i0) ? acc[nt][0] : ((jb     == i0) ? dg0 : 0.0f);
            float p01 = (jb + 1 < i0) ? acc[nt][1] : ((jb + 1 == i0) ? dg0 : 0.0f);
            float p10 = (jb     < i1) ? acc[nt][2] : ((jb     == i1) ? dg1 : 0.0f);
            float p11 = (jb + 1 < i1) ? acc[nt][3] : ((jb + 1 == i1) ? dg1 : 0.0f);
            sm.B.PT[jb][i0]     = p00;
            sm.B.PT[jb + 1][i0] = p01;
            sm.B.PT[jb][i1]     = p10;
            sm.B.PT[jb + 1][i1] = p11;
        }
        #pragma unroll
        for (int p = 0; p < 4; p++) {
            int f = p * 256 + tid;
            int row = f >> 4, col = (f & 15) * 4;
            *(float4*)&sm.C.v[row][col] = vreg[p];
        }
        __syncthreads();

        // ---- GEMM2 (MMA): O[t][v] = rtT^T . S  +  PT^T . v ----
        #pragma unroll
        for (int nt = 0; nt < 4; nt++)
            #pragma unroll
            for (int q = 0; q < 4; q++) acc[nt][q] = 0.0f;

        #pragma unroll
        for (int ks = 0; ks < 8; ks++) {       // S term (reduction over k)
            const int k0 = ks * 8 + tg;
            const int k1r = k0 + 4;
            unsigned a0 = tf32_of(sm.A.rtT[k0][mw + g]);
            unsigned a1 = tf32_of(sm.A.rtT[k0][mw + g + 8]);
            unsigned a2 = tf32_of(sm.A.rtT[k1r][mw + g]);
            unsigned a3 = tf32_of(sm.A.rtT[k1r][mw + g + 8]);
            #pragma unroll
            for (int nt = 0; nt < 4; nt++) {
                unsigned b0 = tf32_of(sm.S[k0][nw + nt * 8 + g]);
                unsigned b1 = tf32_of(sm.S[k1r][nw + nt * 8 + g]);
                mma16n8k8(acc[nt], a0, a1, a2, a3, b0, b1);
            }
        }
        #pragma unroll
        for (int ks = 0; ks < 8; ks++) {       // P.v term (reduction over j)
            const int j0 = ks * 8 + tg;
            const int j1 = j0 + 4;
            unsigned a0 = tf32_of(sm.B.PT[j0][mw + g]);
            unsigned a1 = tf32_of(sm.B.PT[j0][mw + g + 8]);
            unsigned a2 = tf32_of(sm.B.PT[j1][mw + g]);
            unsigned a3 = tf32_of(sm.B.PT[j1][mw + g + 8]);
            #pragma unroll
            for (int nt = 0; nt < 4; nt++) {
                unsigned b0 = tf32_of(sm.C.v[j0][nw + nt * 8 + g]);
                unsigned b1 = tf32_of(sm.C.v[j1][nw + nt * 8 + g]);
                mma16n8k8(acc[nt], a0, a1, a2, a3, b0, b1);
            }
        }

        float* op = out + ((size_t)bh * Tt + t0) * Vv;
        #pragma unroll
        for (int nt = 0; nt < 4; nt++) {
            int col = nw + nt * 8 + 2 * tg;
            *(float2*)&op[(size_t)(mw + g)     * Vv + col] = make_float2(acc[nt][0], acc[nt][1]);
            *(float2*)&op[(size_t)(mw + g + 8) * Vv + col] = make_float2(acc[nt][2], acc[nt][3]);
        }
        __syncthreads();
    }
}

// ---------------- launch ----------------
extern "C" void kernel_launch(void* const* d_in, const int* in_sizes, int n_in,
                              void* d_out, int out_size)
{
    const float* r  = (const float*)d_in[0];
    const float* k  = (const float*)d_in[1];
    const float* v  = (const float*)d_in[2];
    const float* w  = (const float*)d_in[3];
    const float* u  = (const float*)d_in[4];
    const float* st = (const float*)d_in[5];
    float* out = (float*)d_out;

    static bool configured = false;
    if (!configured) {
        cudaFuncSetAttribute(k1_chunk, cudaFuncAttributeMaxDynamicSharedMemorySize,
                             (int)sizeof(K1Smem));
        cudaFuncSetAttribute(k3_out, cudaFuncAttributeMaxDynamicSharedMemorySize,
                             (int)sizeof(K3Smem));
        configured = true;
    }

    k1_chunk<<<dim3(NCk / 2, BH), 256, sizeof(K1Smem)>>>(k, v, w);
    k2_scan<<<dim3(4, BH), 256>>>(st, out);
    k3_out<<<dim3(NCk / 2, BH), 256, sizeof(K3Smem)>>>(r, k, v, w, u, out);
}

// round 10
// speedup vs baseline: 1.4938x; 1.1477x over previous
#include <cuda_runtime.h>

// Problem constants
#define Bb 2
#define Hh 16
#define Tt 2048
#define Kk 64
#define Vv 64
#define Cc 64                 // chunk length
#define NCk (Tt/Cc)           // 32 chunks
#define BH (Bb*Hh)            // 32
#define OUT_T_SIZE (BH*Tt*Vv) // floats of 'out' before state_f
#define PAD 72                // smem row stride (conflict-free fragment loads)

// ---------------- scratch (static __device__, no allocation) ----------------
__device__ float g_aC[BH*NCk*Kk];                   // chunk total decay
__device__ float g_dS[(size_t)BH*NCk*Kk*Vv];        // chunk state delta
__device__ float g_Sc[(size_t)BH*NCk*Kk*Vv];        // state at chunk start
__device__ float g_rt[(size_t)BH*Tt*Kk];            // r~ transposed [bh][c][k][t], tf32-rounded

// ---------------- helpers ----------------
__device__ __forceinline__ void cp_async16(void* smem_dst, const void* gmem_src) {
    unsigned sa = (unsigned)__cvta_generic_to_shared(smem_dst);
    asm volatile("cp.async.cg.shared.global [%0], [%1], 16;" :: "r"(sa), "l"(gmem_src));
}
__device__ __forceinline__ void cp_async_wait_all() {
    asm volatile("cp.async.commit_group;");
    asm volatile("cp.async.wait_group 0;");
}
__device__ __forceinline__ unsigned tf32_of(float x) {
    unsigned u;
    asm("cvt.rna.tf32.f32 %0, %1;" : "=r"(u) : "f"(x));
    return u;
}
__device__ __forceinline__ float tf32r(float x) {       // round-to-tf32, keep as float
    return __uint_as_float(tf32_of(x));
}
// D(16x8) += A(16x8,row) * B(8x8,col) ; tf32 inputs, fp32 accumulate
__device__ __forceinline__ void mma16n8k8(float* d,
    unsigned a0, unsigned a1, unsigned a2, unsigned a3,
    unsigned b0, unsigned b1)
{
    asm volatile(
        "mma.sync.aligned.m16n8k8.row.col.f32.tf32.tf32.f32 "
        "{%0,%1,%2,%3}, {%4,%5,%6,%7}, {%8,%9}, {%0,%1,%2,%3};"
        : "+f"(d[0]), "+f"(d[1]), "+f"(d[2]), "+f"(d[3])
        : "r"(a0), "r"(a1), "r"(a2), "r"(a3), "r"(b0), "r"(b1));
}
__device__ __forceinline__ float4 warp_prod_scan4(float4 a) {
    const int lane = threadIdx.x & 31;
    #pragma unroll
    for (int off = 1; off < 32; off <<= 1) {
        float x0 = __shfl_up_sync(0xffffffffu, a.x, off);
        float x1 = __shfl_up_sync(0xffffffffu, a.y, off);
        float x2 = __shfl_up_sync(0xffffffffu, a.z, off);
        float x3 = __shfl_up_sync(0xffffffffu, a.w, off);
        if (lane >= off) { a.x *= x0; a.y *= x1; a.z *= x2; a.w *= x3; }
    }
    return a;
}
__device__ __forceinline__ float4 shfl_up1_or_one4(float4 a) {
    const int lane = threadIdx.x & 31;
    float4 r;
    r.x = __shfl_up_sync(0xffffffffu, a.x, 1);
    r.y = __shfl_up_sync(0xffffffffu, a.y, 1);
    r.z = __shfl_up_sync(0xffffffffu, a.z, 1);
    r.w = __shfl_up_sync(0xffffffffu, a.w, 1);
    if (lane == 0) r = make_float4(1.f, 1.f, 1.f, 1.f);
    return r;
}
__device__ __forceinline__ float4 shfl31_4(float4 a) {
    float4 r;
    r.x = __shfl_sync(0xffffffffu, a.x, 31);
    r.y = __shfl_sync(0xffffffffu, a.y, 31);
    r.z = __shfl_sync(0xffffffffu, a.z, 31);
    r.w = __shfl_sync(0xffffffffu, a.w, 31);
    return r;
}
__device__ __forceinline__ float4 fmax4(float4 a, float e) {
    return make_float4(fmaxf(a.x, e), fmaxf(a.y, e), fmaxf(a.z, e), fmaxf(a.w, e));
}

// ================= kernel A: scan + dS + P + O_intra =================
// Mid-chunk normalization m = prod(rows 0..31), q_full = prod(rows 32..63), A_full = m*q_full.
//  khT[k][t] = k*m/incl (half0: k*m/p, half1: k/q)           -> sfx*k = khT * q_full[k]
//  rhT[k][t] = r~/m  (half0: r*pre/m, half1: r*pre2)
//  rt (global) = r~   (half0: r*pre, half1: r*m*pre2)
//  dS[k][v] = q_full[k] * sum_t khT[k][t] v[t][v]
//  P[i][j]  = sum_k rh[k][i] khT[k][j] (j<i), diag (j==i), 0 ; O_intra = P.v -> out
struct KASmem {
    union { float w[Cc][PAD]; float khT[Kk][PAD]; } A;
    union { float r[Cc][PAD]; float rhT[Kk][PAD]; } B;
    union { float k[Cc][PAD]; float PT[Cc][PAD]; } C;
    float v[Cc][PAD];
    float dp[8][66];
    float diag[Cc];
    float sK[Kk];       // q_full per k-column
};

__global__ __launch_bounds__(256, 3) void kA_chunk(
    const float* __restrict__ r, const float* __restrict__ k,
    const float* __restrict__ v, const float* __restrict__ w,
    const float* __restrict__ u, float* __restrict__ out)
{
    extern __shared__ char smem_raw[];
    KASmem& sm = *reinterpret_cast<KASmem*>(smem_raw);

    const int bh = blockIdx.y;
    const int h  = bh & (Hh - 1);
    const int tid  = threadIdx.x;
    const int lane = tid & 31;
    const int wi   = tid >> 5;
    const int g  = lane >> 2;      // mma groupID
    const int tg = lane & 3;       // mma thread-in-group
    const int mw = (wi & 3) * 16;  // warp output row base
    const int nw = (wi >> 2) * 32; // warp output col base

    #pragma unroll 1
    for (int half = 0; half < 2; half++) {
        const int c  = blockIdx.x + half * (NCk / 2);
        const int t0 = c * Cc;

        // ---- stage w, r, k, v row-major via cp.async ----
        {
            const float4* wp = (const float4*)(w + ((size_t)h  * Tt + t0) * Kk);
            const float4* rp = (const float4*)(r + ((size_t)bh * Tt + t0) * Kk);
            const float4* kp = (const float4*)(k + ((size_t)bh * Tt + t0) * Kk);
            const float4* vp = (const float4*)(v + ((size_t)bh * Tt + t0) * Vv);
            #pragma unroll
            for (int i = tid; i < Cc * Kk / 4; i += 256) {
                int t = i >> 4, k0 = (i & 15) * 4;
                cp_async16(&sm.A.w[t][k0], &wp[i]);
                cp_async16(&sm.B.r[t][k0], &rp[i]);
                cp_async16(&sm.C.k[t][k0], &kp[i]);
                cp_async16(&sm.v[t][k0],   &vp[i]);
            }
            cp_async_wait_all();
        }
        __syncthreads();

        // ---- scan phase: read rows into regs, compute all normalized forms ----
        float4 kh0[2], kh1[2], rh0[2], rh1[2];
        {
            float dA = 0.0f, dB = 0.0f;
            #pragma unroll
            for (int gg = 0; gg < 2; gg++) {
                const int kk4 = wi * 8 + gg * 4;
                float4 w0 = fmax4(*(const float4*)&sm.A.w[lane][kk4],      1e-6f);
                float4 w1 = fmax4(*(const float4*)&sm.A.w[32 + lane][kk4], 1e-6f);
                float4 r0 = *(const float4*)&sm.B.r[lane][kk4];
                float4 r1 = *(const float4*)&sm.B.r[32 + lane][kk4];
                float4 c0 = *(const float4*)&sm.C.k[lane][kk4];
                float4 c1 = *(const float4*)&sm.C.k[32 + lane][kk4];

                float4 p = warp_prod_scan4(w0);     // prod rows 0..lane
                float4 q = warp_prod_scan4(w1);     // prod rows 32..32+lane
                float4 m    = shfl31_4(p);          // prod rows 0..31
                float4 qf   = shfl31_4(q);          // prod rows 32..63
                float4 pre  = shfl_up1_or_one4(p);
                float4 pre2 = shfl_up1_or_one4(q);
                float4 u4 = *(const float4*)&u[h * Kk + kk4];

                dA = fmaf(r0.x * c0.x, u4.x, dA); dA = fmaf(r0.y * c0.y, u4.y, dA);
                dA = fmaf(r0.z * c0.z, u4.z, dA); dA = fmaf(r0.w * c0.w, u4.w, dA);
                dB = fmaf(r1.x * c1.x, u4.x, dB); dB = fmaf(r1.y * c1.y, u4.y, dB);
                dB = fmaf(r1.z * c1.z, u4.z, dB); dB = fmaf(r1.w * c1.w, u4.w, dB);

                // normalized forms (pre-rounded to tf32)
                kh0[gg] = make_float4(tf32r(c0.x * m.x / p.x), tf32r(c0.y * m.y / p.y),
                                      tf32r(c0.z * m.z / p.z), tf32r(c0.w * m.w / p.w));
                kh1[gg] = make_float4(tf32r(c1.x / q.x), tf32r(c1.y / q.y),
                                      tf32r(c1.z / q.z), tf32r(c1.w / q.w));
                rh0[gg] = make_float4(tf32r(r0.x * pre.x / m.x), tf32r(r0.y * pre.y / m.y),
                                      tf32r(r0.z * pre.z / m.z), tf32r(r0.w * pre.w / m.w));
                rh1[gg] = make_float4(tf32r(r1.x * pre2.x), tf32r(r1.y * pre2.y),
                                      tf32r(r1.z * pre2.z), tf32r(r1.w * pre2.w));

                // r~ to global (transposed [k][t], tf32-rounded), coalesced per kk
                {
                    float* rtb = g_rt + ((size_t)(bh * NCk + c)) * Kk * Cc;
                    float rt0v[4] = {tf32r(r0.x * pre.x), tf32r(r0.y * pre.y),
                                     tf32r(r0.z * pre.z), tf32r(r0.w * pre.w)};
                    float rt1v[4] = {tf32r(r1.x * (m.x * pre2.x)), tf32r(r1.y * (m.y * pre2.y)),
                                     tf32r(r1.z * (m.z * pre2.z)), tf32r(r1.w * (m.w * pre2.w))};
                    #pragma unroll
                    for (int cc = 0; cc < 4; cc++) {
                        rtb[(kk4 + cc) * Cc + lane]      = rt0v[cc];
                        rtb[(kk4 + cc) * Cc + 32 + lane] = rt1v[cc];
                    }
                }
                if (lane == 0) {
                    float4 aC;
                    aC.x = m.x * qf.x; aC.y = m.y * qf.y;
                    aC.z = m.z * qf.z; aC.w = m.w * qf.w;
                    *(float4*)&g_aC[(bh * NCk + c) * Kk + kk4] = aC;
                    *(float4*)&sm.sK[kk4] = qf;
                }
            }
            sm.dp[wi][lane]      = dA;
            sm.dp[wi][32 + lane] = dB;
        }
        __syncthreads();   // all row-major reads complete before transposed writes

        // ---- transposed conflict-free writes into dead input unions ----
        #pragma unroll
        for (int gg = 0; gg < 2; gg++) {
            const int kk4 = wi * 8 + gg * 4;
            sm.A.khT[kk4 + 0][lane] = kh0[gg].x; sm.A.khT[kk4 + 1][lane] = kh0[gg].y;
            sm.A.khT[kk4 + 2][lane] = kh0[gg].z; sm.A.khT[kk4 + 3][lane] = kh0[gg].w;
            sm.A.khT[kk4 + 0][32 + lane] = kh1[gg].x; sm.A.khT[kk4 + 1][32 + lane] = kh1[gg].y;
            sm.A.khT[kk4 + 2][32 + lane] = kh1[gg].z; sm.A.khT[kk4 + 3][32 + lane] = kh1[gg].w;
            sm.B.rhT[kk4 + 0][lane] = rh0[gg].x; sm.B.rhT[kk4 + 1][lane] = rh0[gg].y;
            sm.B.rhT[kk4 + 2][lane] = rh0[gg].z; sm.B.rhT[kk4 + 3][lane] = rh0[gg].w;
            sm.B.rhT[kk4 + 0][32 + lane] = rh1[gg].x; sm.B.rhT[kk4 + 1][32 + lane] = rh1[gg].y;
            sm.B.rhT[kk4 + 2][32 + lane] = rh1[gg].z; sm.B.rhT[kk4 + 3][32 + lane] = rh1[gg].w;
        }
        __syncthreads();
        if (tid < Cc) {
            float d = 0.0f;
            #pragma unroll
            for (int j = 0; j < 8; j++) d += sm.dp[j][tid];
            sm.diag[tid] = d;
        }
        __syncthreads();

        float acc[4][4];

        // ---- dS MMA: dS[k][v] = sK[k] * sum_t khT[k][t] v[t][v] ----
        // A row-major (m=k-dim, kd=t): a = khT[mw+g(+8)][ks*8+tg(+4)]
        #pragma unroll
        for (int nt = 0; nt < 4; nt++)
            #pragma unroll
            for (int q2 = 0; q2 < 4; q2++) acc[nt][q2] = 0.0f;
        #pragma unroll
        for (int ks = 0; ks < 8; ks++) {
            const int td0 = ks * 8 + tg;
            const int td1 = td0 + 4;
            unsigned a0 = __float_as_uint(sm.A.khT[mw + g][td0]);
            unsigned a1 = __float_as_uint(sm.A.khT[mw + g + 8][td0]);
            unsigned a2 = __float_as_uint(sm.A.khT[mw + g][td1]);
            unsigned a3 = __float_as_uint(sm.A.khT[mw + g + 8][td1]);
            #pragma unroll
            for (int nt = 0; nt < 4; nt++) {
                unsigned b0 = tf32_of(sm.v[td0][nw + nt * 8 + g]);
                unsigned b1 = tf32_of(sm.v[td1][nw + nt * 8 + g]);
                mma16n8k8(acc[nt], a0, a1, a2, a3, b0, b1);
            }
        }
        {
            float s0 = sm.sK[mw + g], s1 = sm.sK[mw + g + 8];
            float* dsp = g_dS + (size_t)(bh * NCk + c) * Kk * Vv;
            #pragma unroll
            for (int nt = 0; nt < 4; nt++) {
                int col = nw + nt * 8 + 2 * tg;
                *(float2*)&dsp[(size_t)(mw + g)     * Vv + col] =
                    make_float2(acc[nt][0] * s0, acc[nt][1] * s0);
                *(float2*)&dsp[(size_t)(mw + g + 8) * Vv + col] =
                    make_float2(acc[nt][2] * s1, acc[nt][3] * s1);
            }
        }

        // ---- P MMA: P[i][j] = sum_k rhT[k][i] khT[k][j] ----
        #pragma unroll
        for (int nt = 0; nt < 4; nt++)
            #pragma unroll
            for (int q2 = 0; q2 < 4; q2++) acc[nt][q2] = 0.0f;
        #pragma unroll
        for (int ks = 0; ks < 8; ks++) {
            const int kd0 = ks * 8 + tg;
            const int kd1 = kd0 + 4;
            unsigned a0 = __float_as_uint(sm.B.rhT[kd0][mw + g]);
            unsigned a1 = __float_as_uint(sm.B.rhT[kd0][mw + g + 8]);
            unsigned a2 = __float_as_uint(sm.B.rhT[kd1][mw + g]);
            unsigned a3 = __float_as_uint(sm.B.rhT[kd1][mw + g + 8]);
            #pragma unroll
            for (int nt = 0; nt < 4; nt++) {
                unsigned b0 = __float_as_uint(sm.A.khT[kd0][nw + nt * 8 + g]);
                unsigned b1 = __float_as_uint(sm.A.khT[kd1][nw + nt * 8 + g]);
                mma16n8k8(acc[nt], a0, a1, a2, a3, b0, b1);
            }
        }
        // mask + store P^T (tf32-rounded) into C (k_rm dead since scan)
        {
            float dg0 = sm.diag[mw + g];
            float dg1 = sm.diag[mw + g + 8];
            #pragma unroll
            for (int nt = 0; nt < 4; nt++) {
                int jb = nw + nt * 8 + 2 * tg;
                int i0 = mw + g, i1 = mw + g + 8;
                sm.C.PT[jb][i0]     = tf32r((jb     < i0) ? acc[nt][0] : ((jb     == i0) ? dg0 : 0.0f));
                sm.C.PT[jb + 1][i0] = tf32r((jb + 1 < i0) ? acc[nt][1] : ((jb + 1 == i0) ? dg0 : 0.0f));
                sm.C.PT[jb][i1]     = tf32r((jb     < i1) ? acc[nt][2] : ((jb     == i1) ? dg1 : 0.0f));
                sm.C.PT[jb + 1][i1] = tf32r((jb + 1 < i1) ? acc[nt][3] : ((jb + 1 == i1) ? dg1 : 0.0f));
            }
        }
        __syncthreads();

        // ---- O_intra MMA: O[t][v] = sum_j PT[j][t] v[j][v]  -> out ----
        #pragma unroll
        for (int nt = 0; nt < 4; nt++)
            #pragma unroll
            for (int q2 = 0; q2 < 4; q2++) acc[nt][q2] = 0.0f;
        #pragma unroll
        for (int ks = 0; ks < 8; ks++) {
            const int jd0 = ks * 8 + tg;
            const int jd1 = jd0 + 4;
            unsigned a0 = __float_as_uint(sm.C.PT[jd0][mw + g]);
            unsigned a1 = __float_as_uint(sm.C.PT[jd0][mw + g + 8]);
            unsigned a2 = __float_as_uint(sm.C.PT[jd1][mw + g]);
            unsigned a3 = __float_as_uint(sm.C.PT[jd1][mw + g + 8]);
            #pragma unroll
            for (int nt = 0; nt < 4; nt++) {
                unsigned b0 = tf32_of(sm.v[jd0][nw + nt * 8 + g]);
                unsigned b1 = tf32_of(sm.v[jd1][nw + nt * 8 + g]);
                mma16n8k8(acc[nt], a0, a1, a2, a3, b0, b1);
            }
        }
        {
            float* op = out + ((size_t)bh * Tt + t0) * Vv;
            #pragma unroll
            for (int nt = 0; nt < 4; nt++) {
                int col = nw + nt * 8 + 2 * tg;
                *(float2*)&op[(size_t)(mw + g)     * Vv + col] = make_float2(acc[nt][0], acc[nt][1]);
                *(float2*)&op[(size_t)(mw + g + 8) * Vv + col] = make_float2(acc[nt][2], acc[nt][3]);
            }
        }
        __syncthreads();   // before restaging next chunk
    }
}

// ================= kernel 2: sequential chunk-level state scan =================
__global__ __launch_bounds__(256) void k2_scan(
    const float* __restrict__ state_in, float* __restrict__ out)
{
    const int bh  = blockIdx.y;
    const int tid = threadIdx.x;
    const int fi  = blockIdx.x * 256 + tid;
    const int krow = fi >> 4;

    float4 S = ((const float4*)(state_in + (size_t)bh * Kk * Vv))[fi];

    const float*  aCb = g_aC + bh * NCk * Kk;
    const float4* dSb = (const float4*)(g_dS + (size_t)bh * NCk * Kk * Vv);
    float4*       Scb = (float4*)(g_Sc + (size_t)bh * NCk * Kk * Vv);

    float4 db[2][4];
    float  ab[2][4];

    #pragma unroll
    for (int j = 0; j < 4; j++) {
        db[0][j] = dSb[(size_t)j * 1024 + fi];
        ab[0][j] = aCb[j * Kk + krow];
    }

    #pragma unroll 1
    for (int gq = 0; gq < NCk / 4; gq++) {
        const int cur = gq & 1;
        if (gq + 1 < NCk / 4) {
            #pragma unroll
            for (int j = 0; j < 4; j++) {
                int c = (gq + 1) * 4 + j;
                db[cur ^ 1][j] = dSb[(size_t)c * 1024 + fi];
                ab[cur ^ 1][j] = aCb[c * Kk + krow];
            }
        }
        #pragma unroll
        for (int j = 0; j < 4; j++) {
            int c = gq * 4 + j;
            Scb[(size_t)c * 1024 + fi] = S;
            float a = ab[cur][j]; float4 d = db[cur][j];
            S.x = fmaf(a, S.x, d.x); S.y = fmaf(a, S.y, d.y);
            S.z = fmaf(a, S.z, d.z); S.w = fmaf(a, S.w, d.w);
        }
    }

    ((float4*)(out + (size_t)OUT_T_SIZE + (size_t)bh * Kk * Vv))[fi] = S;
}

// ================= kernel B: cross-chunk term, O += rt . S =================
struct KBSmem {
    float rtT[Kk][PAD];   // [k][t], tf32-rounded already
    float S[Kk][PAD];     // [k][v]
};

__global__ __launch_bounds__(256, 6) void kB_cross(
    float* __restrict__ out)
{
    extern __shared__ char smem_raw[];
    KBSmem& sm = *reinterpret_cast<KBSmem*>(smem_raw);

    const int c  = blockIdx.x;
    const int bh = blockIdx.y;
    const int t0 = c * Cc;
    const int tid  = threadIdx.x;
    const int lane = tid & 31;
    const int wi   = tid >> 5;
    const int g  = lane >> 2;
    const int tg = lane & 3;
    const int mw = (wi & 3) * 16;
    const int nw = (wi >> 2) * 32;

    // ---- stage rtT + Sc ----
    {
        const float4* rp = (const float4*)(g_rt + ((size_t)(bh * NCk + c)) * Kk * Cc);
        const float4* Sp = (const float4*)(g_Sc + (size_t)(bh * NCk + c) * Kk * Vv);
        #pragma unroll
        for (int i = tid; i < Kk * Cc / 4; i += 256) {
            int row = i >> 4, c4 = (i & 15) * 4;
            cp_async16(&sm.rtT[row][c4], &rp[i]);
            cp_async16(&sm.S[row][c4],   &Sp[i]);
        }
        cp_async_wait_all();
    }
    __syncthreads();

    // ---- O_cross MMA: O[t][v] += sum_k rtT[k][t] S[k][v] ----
    float acc[4][4];
    #pragma unroll
    for (int nt = 0; nt < 4; nt++)
        #pragma unroll
        for (int q2 = 0; q2 < 4; q2++) acc[nt][q2] = 0.0f;

    #pragma unroll
    for (int ks = 0; ks < 8; ks++) {
        const int kd0 = ks * 8 + tg;
        const int kd1 = kd0 + 4;
        unsigned a0 = __float_as_uint(sm.rtT[kd0][mw + g]);
        unsigned a1 = __float_as_uint(sm.rtT[kd0][mw + g + 8]);
        unsigned a2 = __float_as_uint(sm.rtT[kd1][mw + g]);
        unsigned a3 = __float_as_uint(sm.rtT[kd1][mw + g + 8]);
        #pragma unroll
        for (int nt = 0; nt < 4; nt++) {
            unsigned b0 = tf32_of(sm.S[kd0][nw + nt * 8 + g]);
            unsigned b1 = tf32_of(sm.S[kd1][nw + nt * 8 + g]);
            mma16n8k8(acc[nt], a0, a1, a2, a3, b0, b1);
        }
    }

    // ---- read-modify-write out ----
    float* op = out + ((size_t)bh * Tt + t0) * Vv;
    #pragma unroll
    for (int nt = 0; nt < 4; nt++) {
        int col = nw + nt * 8 + 2 * tg;
        float2* p0 = (float2*)&op[(size_t)(mw + g)     * Vv + col];
        float2* p1 = (float2*)&op[(size_t)(mw + g + 8) * Vv + col];
        float2 o0 = *p0, o1 = *p1;
        o0.x += acc[nt][0]; o0.y += acc[nt][1];
        o1.x += acc[nt][2]; o1.y += acc[nt][3];
        *p0 = o0; *p1 = o1;
    }
}

// ---------------- launch ----------------
extern "C" void kernel_launch(void* const* d_in, const int* in_sizes, int n_in,
                              void* d_out, int out_size)
{
    const float* r  = (const float*)d_in[0];
    const float* k  = (const float*)d_in[1];
    const float* v  = (const float*)d_in[2];
    const float* w  = (const float*)d_in[3];
    const float* u  = (const float*)d_in[4];
    const float* st = (const float*)d_in[5];
    float* out = (float*)d_out;

    static bool configured = false;
    if (!configured) {
        cudaFuncSetAttribute(kA_chunk, cudaFuncAttributeMaxDynamicSharedMemorySize,
                             (int)sizeof(KASmem));
        cudaFuncSetAttribute(kB_cross, cudaFuncAttributeMaxDynamicSharedMemorySize,
                             (int)sizeof(KBSmem));
        configured = true;
    }

    kA_chunk<<<dim3(NCk / 2, BH), 256, sizeof(KASmem)>>>(r, k, v, w, u, out);
    k2_scan<<<dim3(4, BH), 256>>>(st, out);
    kB_cross<<<dim3(NCk, BH), 256, sizeof(KBSmem)>>>(out);
}